// round 12
// baseline (speedup 1.0000x reference)
#include <cuda_runtime.h>
#include <cuda_fp16.h>
#include <cuda_bf16.h>

// ============================================================================
// GCN 2-layer on GB300, round 11:
//  - revert to R9 topology: fused pre-fork degree histogram, 8-edge agg
//  - keep warp-aggregated k_assign (1 global atomic per warp)
//  - NEW: agg1 + gemm2 fused in one kernel (h lives in smem; g_B deleted)
// ============================================================================

#define NN   100000
#define EMAX 1600000

__device__ int   g_deg_out[NN];
__device__ int   g_deg_in[NN];
__device__ int   g_csr_ptr[NN];
__device__ int   g_cursor[NN];
__device__ int   g_csr_src[EMAX];
__device__ int   g_total;
__device__ __align__(16) __half g_A[NN * 64];     // gemm1 out -> agg1; gemm2 out -> agg2
__device__ __align__(16) __half g_A2[NN * 64];    // gemm2 output (dout-scaled)
__device__ __align__(16) __half g_W1t[64 * 128];  // W1^T [n][k] half
__device__ __align__(16) __half g_W2t[64 * 64];   // W2^T [n][k] half

// ---- fused prep: zero degree counters + total + transpose/convert weights ----
__global__ void k_prep(const float* __restrict__ W1, const float* __restrict__ W2, int n) {
    int t = blockIdx.x * blockDim.x + threadIdx.x;
    if (t < n) { g_deg_out[t] = 0; g_deg_in[t] = 0; }
    if (t == 0) g_total = 0;
    if (t < 64 * 128) {
        int nn_ = t >> 7, k = t & 127;
        g_W1t[t] = __float2half(W1[k * 64 + nn_]);
    } else if (t < 64 * 128 + 64 * 64) {
        int u = t - 64 * 128;
        int nn_ = u >> 6, k = u & 63;
        g_W2t[u] = __float2half(W2[k * 64 + nn_]);
    }
}

// ---- fused degree histogram: 4 edges/thread, both degrees in one pass ----
__global__ void k_deg(const int* __restrict__ src, const int* __restrict__ dst, int E) {
    int t = blockIdx.x * blockDim.x + threadIdx.x;
    int e = t * 4;
    if (e + 3 < E) {
        int4 s4 = *reinterpret_cast<const int4*>(src + e);
        int4 d4 = *reinterpret_cast<const int4*>(dst + e);
        atomicAdd(&g_deg_out[s4.x], 1);
        atomicAdd(&g_deg_out[s4.y], 1);
        atomicAdd(&g_deg_out[s4.z], 1);
        atomicAdd(&g_deg_out[s4.w], 1);
        atomicAdd(&g_deg_in[d4.x], 1);
        atomicAdd(&g_deg_in[d4.y], 1);
        atomicAdd(&g_deg_in[d4.z], 1);
        atomicAdd(&g_deg_in[d4.w], 1);
    } else {
        for (; e < E; e++) {
            atomicAdd(&g_deg_out[src[e]], 1);
            atomicAdd(&g_deg_in[dst[e]], 1);
        }
    }
}

// ---- segment assignment: warp-aggregated (1 atomic per warp) ----
__global__ void k_assign(int n) {
    int i = blockIdx.x * blockDim.x + threadIdx.x;
    int lane = threadIdx.x & 31;
    int d = (i < n) ? g_deg_in[i] : 0;
    int pre = d;
#pragma unroll
    for (int off = 1; off < 32; off <<= 1) {
        int v = __shfl_up_sync(0xffffffffu, pre, off);
        if (lane >= off) pre += v;
    }
    int tot = __shfl_sync(0xffffffffu, pre, 31);
    int base = 0;
    if (lane == 31) base = atomicAdd(&g_total, tot);
    base = __shfl_sync(0xffffffffu, base, 31);
    int p = base + pre - d;
    if (i < n) {
        g_csr_ptr[i] = p;
        g_cursor[i]  = p;
    }
}

// ---- CSR fill: 4 edges/thread ----
__global__ void k_fill(const int* __restrict__ src, const int* __restrict__ dst, int E) {
    int t = blockIdx.x * blockDim.x + threadIdx.x;
    int e = t * 4;
    if (e + 3 < E) {
        int4 s4 = *reinterpret_cast<const int4*>(src + e);
        int4 d4 = *reinterpret_cast<const int4*>(dst + e);
        g_csr_src[atomicAdd(&g_cursor[d4.x], 1)] = s4.x;
        g_csr_src[atomicAdd(&g_cursor[d4.y], 1)] = s4.y;
        g_csr_src[atomicAdd(&g_cursor[d4.z], 1)] = s4.z;
        g_csr_src[atomicAdd(&g_cursor[d4.w], 1)] = s4.w;
    } else {
        for (; e < E; e++)
            g_csr_src[atomicAdd(&g_cursor[dst[e]], 1)] = src[e];
    }
}

// ============================================================================
// GEMM1 (HMMA): g_A[r][c] = fp16( (x[r,:] @ W1[:,c]) * rsqrt(max(deg_out,1)) )
// Block 128x64, 256 threads, K=128 chunked by 32, padded smem stride 40.
// ============================================================================
#define XS 40

__global__ void k_gemm1(const float* __restrict__ Xf, int n) {
    __shared__ __align__(16) __half sX[128 * XS];
    __shared__ __align__(16) __half sW[64 * XS];

    int tid = threadIdx.x;
    int lane = tid & 31;
    int warp = tid >> 5;
    int warp_m = warp & 3;
    int warp_n = warp >> 2;
    int g = lane >> 2;
    int tig = lane & 3;
    int row0 = blockIdx.x * 128;

    float acc[2][4][4];
#pragma unroll
    for (int mt = 0; mt < 2; mt++)
#pragma unroll
        for (int nt = 0; nt < 4; nt++)
#pragma unroll
            for (int c = 0; c < 4; c++) acc[mt][nt][c] = 0.f;

#pragma unroll
    for (int kc = 0; kc < 128; kc += 32) {
#pragma unroll
        for (int p = 0; p < 4; p++) {
            int l = tid + p * 256;
            int r = l >> 3, c4 = l & 7;
            int gr = row0 + r;
            if (gr < n) {
                float4 v = *reinterpret_cast<const float4*>(Xf + (size_t)gr * 128 + kc + c4 * 4);
                *reinterpret_cast<__half2*>(&sX[r * XS + c4 * 4])     = __floats2half2_rn(v.x, v.y);
                *reinterpret_cast<__half2*>(&sX[r * XS + c4 * 4 + 2]) = __floats2half2_rn(v.z, v.w);
            }
        }
        {
            int r = tid >> 2, q = tid & 3;
            *reinterpret_cast<uint4*>(&sW[r * XS + q * 8]) =
                *reinterpret_cast<const uint4*>(g_W1t + (size_t)r * 128 + kc + q * 8);
        }
        __syncthreads();

#pragma unroll
        for (int k16 = 0; k16 < 32; k16 += 16) {
#pragma unroll
            for (int mt = 0; mt < 2; mt++) {
                int ar = warp_m * 32 + mt * 16;
                unsigned a0 = *reinterpret_cast<unsigned*>(&sX[(ar + g) * XS + k16 + tig * 2]);
                unsigned a1 = *reinterpret_cast<unsigned*>(&sX[(ar + g + 8) * XS + k16 + tig * 2]);
                unsigned a2 = *reinterpret_cast<unsigned*>(&sX[(ar + g) * XS + k16 + tig * 2 + 8]);
                unsigned a3 = *reinterpret_cast<unsigned*>(&sX[(ar + g + 8) * XS + k16 + tig * 2 + 8]);
#pragma unroll
                for (int nt = 0; nt < 4; nt++) {
                    int col = warp_n * 32 + nt * 8 + g;
                    unsigned b0 = *reinterpret_cast<unsigned*>(&sW[col * XS + k16 + tig * 2]);
                    unsigned b1 = *reinterpret_cast<unsigned*>(&sW[col * XS + k16 + tig * 2 + 8]);
                    float* c = acc[mt][nt];
                    asm volatile(
                        "mma.sync.aligned.m16n8k16.row.col.f32.f16.f16.f32 "
                        "{%0,%1,%2,%3},{%4,%5,%6,%7},{%8,%9},{%0,%1,%2,%3};"
                        : "+f"(c[0]), "+f"(c[1]), "+f"(c[2]), "+f"(c[3])
                        : "r"(a0), "r"(a1), "r"(a2), "r"(a3), "r"(b0), "r"(b1));
                }
            }
        }
        __syncthreads();
    }

#pragma unroll
    for (int mt = 0; mt < 2; mt++) {
        int row = row0 + warp_m * 32 + mt * 16 + g;
        float s0 = (row     < n) ? rsqrtf((float)max(g_deg_out[row], 1))     : 0.f;
        float s1 = (row + 8 < n) ? rsqrtf((float)max(g_deg_out[row + 8], 1)) : 0.f;
#pragma unroll
        for (int nt = 0; nt < 4; nt++) {
            int col = warp_n * 32 + nt * 8 + tig * 2;
            float* c = acc[mt][nt];
            if (row < n)
                *reinterpret_cast<__half2*>(g_A + (size_t)row * 64 + col) =
                    __floats2half2_rn(c[0] * s0, c[1] * s0);
            if (row + 8 < n)
                *reinterpret_cast<__half2*>(g_A + (size_t)(row + 8) * 64 + col) =
                    __floats2half2_rn(c[2] * s1, c[3] * s1);
        }
    }
}

// ============================================================================
// FUSED agg1 + gemm2. Block owns 128 nodes.
// Phase 1: 8 warps x 16 nodes each: h[node] = relu(sum A1[src] * din + b1),
//          written straight into padded smem (stride 72 halfs; bank = 4g+tig,
//          conflict-free for the MMA fetch pattern).
// Phase 2: HMMA mainloop over K=64 straight from smem; epilogue writes g_A2
//          with dout scaling.
// ============================================================================
#define HS 72   // smem row stride (halfs) for the h tile

__global__ void k_agg_gemm2(const float* __restrict__ b1, int n) {
    __shared__ __align__(16) __half sH[128 * HS];   // 18432 B
    __shared__ __align__(16) __half sW[64 * XS];    //  5120 B

    int tid = threadIdx.x;
    int lane = tid & 31;
    int warp = tid >> 5;
    int row0 = blockIdx.x * 128;

    // ---- phase 1: aggregate 16 nodes per warp ----
    {
        int sub = lane & 7;
        int grp = lane >> 3;
        for (int i = 0; i < 16; i++) {
            int lr = warp * 16 + i;          // local row 0..127
            int gw = row0 + lr;
            if (gw >= n) break;
            int s0 = g_csr_ptr[gw];
            int deg = g_deg_in[gw];
            int s1 = s0 + deg;

            float acc[8];
#pragma unroll
            for (int j = 0; j < 8; j++) acc[j] = 0.f;

            for (int base = s0; base < s1; base += 8) {
                int e0 = base + grp;
                int e1 = base + 4 + grp;
                uint4 h0 = make_uint4(0u, 0u, 0u, 0u);
                uint4 h1 = make_uint4(0u, 0u, 0u, 0u);
                if (e0 < s1)
                    h0 = *reinterpret_cast<const uint4*>(g_A + (size_t)g_csr_src[e0] * 64 + sub * 8);
                if (e1 < s1)
                    h1 = *reinterpret_cast<const uint4*>(g_A + (size_t)g_csr_src[e1] * 64 + sub * 8);
                const __half2* p0 = reinterpret_cast<const __half2*>(&h0);
                const __half2* p1 = reinterpret_cast<const __half2*>(&h1);
#pragma unroll
                for (int q = 0; q < 4; q++) {
                    float2 f0 = __half22float2(p0[q]);
                    float2 f1 = __half22float2(p1[q]);
                    acc[q * 2]     += f0.x + f1.x;
                    acc[q * 2 + 1] += f0.y + f1.y;
                }
            }
#pragma unroll
            for (int j = 0; j < 8; j++) {
                acc[j] += __shfl_xor_sync(0xffffffffu, acc[j], 8);
                acc[j] += __shfl_xor_sync(0xffffffffu, acc[j], 16);
            }
            if (grp == 0) {
                float sc = rsqrtf((float)max(deg, 1));
                const float* bp = b1 + sub * 8;
                float o[8];
#pragma unroll
                for (int j = 0; j < 8; j++)
                    o[j] = fmaxf(fmaf(acc[j], sc, bp[j]), 0.f);
                uint4 pack;
                __half2* hp = reinterpret_cast<__half2*>(&pack);
                hp[0] = __floats2half2_rn(o[0], o[1]);
                hp[1] = __floats2half2_rn(o[2], o[3]);
                hp[2] = __floats2half2_rn(o[4], o[5]);
                hp[3] = __floats2half2_rn(o[6], o[7]);
                *reinterpret_cast<uint4*>(&sH[lr * HS + sub * 8]) = pack;
            }
        }
        // zero-pad rows beyond n so the MMA reads zeros
        for (int i = 0; i < 16; i++) {
            int lr = warp * 16 + i;
            int gw = row0 + lr;
            if (gw < n) continue;
            if (lane < 8)
                *reinterpret_cast<uint4*>(&sH[lr * HS + lane * 8]) = make_uint4(0u,0u,0u,0u);
        }
    }

    // load W2 chunk covering K=64 in two 32-chunks into sW on demand below
    __syncthreads();

    // ---- phase 2: gemm2 from smem ----
    int warp_m = warp & 3;
    int warp_n = warp >> 2;
    int g = lane >> 2;
    int tig = lane & 3;

    float acc[2][4][4];
#pragma unroll
    for (int mt = 0; mt < 2; mt++)
#pragma unroll
        for (int nt = 0; nt < 4; nt++)
#pragma unroll
            for (int c = 0; c < 4; c++) acc[mt][nt][c] = 0.f;

#pragma unroll
    for (int kc = 0; kc < 64; kc += 32) {
        {
            int r = tid >> 2, q = tid & 3;
            *reinterpret_cast<uint4*>(&sW[r * XS + q * 8]) =
                *reinterpret_cast<const uint4*>(g_W2t + (size_t)r * 64 + kc + q * 8);
        }
        __syncthreads();

#pragma unroll
        for (int k16 = 0; k16 < 32; k16 += 16) {
#pragma unroll
            for (int mt = 0; mt < 2; mt++) {
                int ar = warp_m * 32 + mt * 16;
                unsigned a0 = *reinterpret_cast<unsigned*>(&sH[(ar + g) * HS + kc + k16 + tig * 2]);
                unsigned a1 = *reinterpret_cast<unsigned*>(&sH[(ar + g + 8) * HS + kc + k16 + tig * 2]);
                unsigned a2 = *reinterpret_cast<unsigned*>(&sH[(ar + g) * HS + kc + k16 + tig * 2 + 8]);
                unsigned a3 = *reinterpret_cast<unsigned*>(&sH[(ar + g + 8) * HS + kc + k16 + tig * 2 + 8]);
#pragma unroll
                for (int nt = 0; nt < 4; nt++) {
                    int col = warp_n * 32 + nt * 8 + g;
                    unsigned b0 = *reinterpret_cast<unsigned*>(&sW[col * XS + k16 + tig * 2]);
                    unsigned b1 = *reinterpret_cast<unsigned*>(&sW[col * XS + k16 + tig * 2 + 8]);
                    float* c = acc[mt][nt];
                    asm volatile(
                        "mma.sync.aligned.m16n8k16.row.col.f32.f16.f16.f32 "
                        "{%0,%1,%2,%3},{%4,%5,%6,%7},{%8,%9},{%0,%1,%2,%3};"
                        : "+f"(c[0]), "+f"(c[1]), "+f"(c[2]), "+f"(c[3])
                        : "r"(a0), "r"(a1), "r"(a2), "r"(a3), "r"(b0), "r"(b1));
                }
            }
        }
        __syncthreads();
    }

#pragma unroll
    for (int mt = 0; mt < 2; mt++) {
        int row = row0 + warp_m * 32 + mt * 16 + g;
        float s0 = (row     < n) ? rsqrtf((float)max(g_deg_out[row], 1))     : 0.f;
        float s1 = (row + 8 < n) ? rsqrtf((float)max(g_deg_out[row + 8], 1)) : 0.f;
#pragma unroll
        for (int nt = 0; nt < 4; nt++) {
            int col = warp_n * 32 + nt * 8 + tig * 2;
            float* c = acc[mt][nt];
            if (row < n)
                *reinterpret_cast<__half2*>(g_A2 + (size_t)row * 64 + col) =
                    __floats2half2_rn(c[0] * s0, c[1] * s0);
            if (row + 8 < n)
                *reinterpret_cast<__half2*>(g_A2 + (size_t)(row + 8) * 64 + col) =
                    __floats2half2_rn(c[2] * s1, c[3] * s1);
        }
    }
}

// ============================================================================
// Final aggregate (layer 2): warp per node, 8 lanes/edge, 8 edges in flight.
// ============================================================================
__global__ void k_agg2(const float* __restrict__ bias, float* __restrict__ outp, int n) {
    int gw = (blockIdx.x * blockDim.x + threadIdx.x) >> 5;
    int lane = threadIdx.x & 31;
    if (gw >= n) return;

    int s0 = g_csr_ptr[gw];
    int deg = g_deg_in[gw];
    int s1 = s0 + deg;
    int sub = lane & 7;
    int grp = lane >> 3;

    float acc[8];
#pragma unroll
    for (int j = 0; j < 8; j++) acc[j] = 0.f;

    for (int base = s0; base < s1; base += 8) {
        int e0 = base + grp;
        int e1 = base + 4 + grp;
        uint4 h0 = make_uint4(0u, 0u, 0u, 0u);
        uint4 h1 = make_uint4(0u, 0u, 0u, 0u);
        if (e0 < s1)
            h0 = *reinterpret_cast<const uint4*>(g_A2 + (size_t)g_csr_src[e0] * 64 + sub * 8);
        if (e1 < s1)
            h1 = *reinterpret_cast<const uint4*>(g_A2 + (size_t)g_csr_src[e1] * 64 + sub * 8);
        const __half2* p0 = reinterpret_cast<const __half2*>(&h0);
        const __half2* p1 = reinterpret_cast<const __half2*>(&h1);
#pragma unroll
        for (int q = 0; q < 4; q++) {
            float2 f0 = __half22float2(p0[q]);
            float2 f1 = __half22float2(p1[q]);
            acc[q * 2]     += f0.x + f1.x;
            acc[q * 2 + 1] += f0.y + f1.y;
        }
    }

#pragma unroll
    for (int j = 0; j < 8; j++) {
        acc[j] += __shfl_xor_sync(0xffffffffu, acc[j], 8);
        acc[j] += __shfl_xor_sync(0xffffffffu, acc[j], 16);
    }

    if (grp == 0) {
        float sc = rsqrtf((float)max(deg, 1));
        const float* bp = bias + sub * 8;
        float o[8];
#pragma unroll
        for (int j = 0; j < 8; j++)
            o[j] = fmaf(acc[j], sc, bp[j]);
        float* op = outp + (size_t)gw * 64 + sub * 8;
        *reinterpret_cast<float4*>(op)     = make_float4(o[0], o[1], o[2], o[3]);
        *reinterpret_cast<float4*>(op + 4) = make_float4(o[4], o[5], o[6], o[7]);
    }
}

extern "C" void kernel_launch(void* const* d_in, const int* in_sizes, int n_in,
                              void* d_out, int out_size) {
    const float* x   = (const float*)d_in[0];
    const int*   src = (const int*)d_in[1];
    const int*   dst = (const int*)d_in[2];
    const float* W1  = (const float*)d_in[3];
    const float* b1  = (const float*)d_in[4];
    const float* W2  = (const float*)d_in[5];
    const float* b2  = (const float*)d_in[6];
    float* out = (float*)d_out;

    const int n = NN;
    const int E = in_sizes[1];

    const int T = 256;
    int grid_e4    = ((E + 3) / 4 + T - 1) / T;
    int grid_nodes = (n + T - 1) / T;
    int grid_gemm  = (n + 127) / 128;
    int grid_agg   = (n * 32 + T - 1) / T;

    cudaStream_t s1;
    cudaStreamCreateWithFlags(&s1, cudaStreamNonBlocking);
    cudaEvent_t evFork, evJoin;
    cudaEventCreateWithFlags(&evFork, cudaEventDisableTiming);
    cudaEventCreateWithFlags(&evJoin, cudaEventDisableTiming);

    // serial prefix: prep, fused degrees
    k_prep<<<grid_nodes, T>>>(W1, W2, n);
    k_deg<<<grid_e4, T>>>(src, dst, E);
    cudaEventRecord(evFork, 0);
    cudaStreamWaitEvent(s1, evFork, 0);

    // branch A (main): GEMM1
    k_gemm1<<<grid_gemm, T>>>(x, n);

    // branch B (s1): warp-agg assign -> CSR fill
    k_assign<<<grid_nodes, T, 0, s1>>>(n);
    k_fill<<<grid_e4, T, 0, s1>>>(src, dst, E);
    cudaEventRecord(evJoin, s1);
    cudaStreamWaitEvent(0, evJoin, 0);

    // fused agg1+gemm2, then final aggregate
    k_agg_gemm2<<<grid_gemm, T>>>(b1, n);
    k_agg2<<<grid_agg, T>>>(b2, out, n);

    cudaEventDestroy(evFork);
    cudaEventDestroy(evJoin);
    cudaStreamDestroy(s1);
}

// round 13
// speedup vs baseline: 1.0736x; 1.0736x over previous
#include <cuda_runtime.h>
#include <cuda_fp16.h>
#include <cuda_bf16.h>

// ============================================================================
// GCN 2-layer on GB300, round 12: revert to R9 topology (131.6us best),
// single change: k_agg runs 16 edges in flight (4 independent uint4 chains).
//   prep -> fused deg -> fork{ gemm1 || assign+fill } -> agg1 -> gemm2 -> agg2
// ============================================================================

#define NN   100000
#define EMAX 1600000

__device__ int   g_deg_out[NN];
__device__ int   g_deg_in[NN];
__device__ int   g_csr_ptr[NN];
__device__ int   g_cursor[NN];
__device__ int   g_csr_src[EMAX];
__device__ int   g_total;
__device__ __align__(16) __half g_A[NN * 64];     // gemm outputs (dout-scaled)
__device__ __align__(16) __half g_B[NN * 64];     // layer-1 hidden (relu out)
__device__ __align__(16) __half g_W1t[64 * 128];  // W1^T [n][k] half
__device__ __align__(16) __half g_W2t[64 * 64];   // W2^T [n][k] half

// ---- fused prep: zero degree counters + total + transpose/convert weights ----
__global__ void k_prep(const float* __restrict__ W1, const float* __restrict__ W2, int n) {
    int t = blockIdx.x * blockDim.x + threadIdx.x;
    if (t < n) { g_deg_out[t] = 0; g_deg_in[t] = 0; }
    if (t == 0) g_total = 0;
    if (t < 64 * 128) {
        int nn_ = t >> 7, k = t & 127;
        g_W1t[t] = __float2half(W1[k * 64 + nn_]);
    } else if (t < 64 * 128 + 64 * 64) {
        int u = t - 64 * 128;
        int nn_ = u >> 6, k = u & 63;
        g_W2t[u] = __float2half(W2[k * 64 + nn_]);
    }
}

// ---- fused degree histogram: 4 edges/thread, both degrees in one pass ----
__global__ void k_deg(const int* __restrict__ src, const int* __restrict__ dst, int E) {
    int t = blockIdx.x * blockDim.x + threadIdx.x;
    int e = t * 4;
    if (e + 3 < E) {
        int4 s4 = *reinterpret_cast<const int4*>(src + e);
        int4 d4 = *reinterpret_cast<const int4*>(dst + e);
        atomicAdd(&g_deg_out[s4.x], 1);
        atomicAdd(&g_deg_out[s4.y], 1);
        atomicAdd(&g_deg_out[s4.z], 1);
        atomicAdd(&g_deg_out[s4.w], 1);
        atomicAdd(&g_deg_in[d4.x], 1);
        atomicAdd(&g_deg_in[d4.y], 1);
        atomicAdd(&g_deg_in[d4.z], 1);
        atomicAdd(&g_deg_in[d4.w], 1);
    } else {
        for (; e < E; e++) {
            atomicAdd(&g_deg_out[src[e]], 1);
            atomicAdd(&g_deg_in[dst[e]], 1);
        }
    }
}

// ---- segment assignment: warp-aggregated (1 global atomic per warp) ----
__global__ void k_assign(int n) {
    int i = blockIdx.x * blockDim.x + threadIdx.x;
    int lane = threadIdx.x & 31;
    int d = (i < n) ? g_deg_in[i] : 0;
    int pre = d;
#pragma unroll
    for (int off = 1; off < 32; off <<= 1) {
        int v = __shfl_up_sync(0xffffffffu, pre, off);
        if (lane >= off) pre += v;
    }
    int tot = __shfl_sync(0xffffffffu, pre, 31);
    int base = 0;
    if (lane == 31) base = atomicAdd(&g_total, tot);
    base = __shfl_sync(0xffffffffu, base, 31);
    int p = base + pre - d;
    if (i < n) {
        g_csr_ptr[i] = p;
        g_cursor[i]  = p;
    }
}

// ---- CSR fill: 4 edges/thread ----
__global__ void k_fill(const int* __restrict__ src, const int* __restrict__ dst, int E) {
    int t = blockIdx.x * blockDim.x + threadIdx.x;
    int e = t * 4;
    if (e + 3 < E) {
        int4 s4 = *reinterpret_cast<const int4*>(src + e);
        int4 d4 = *reinterpret_cast<const int4*>(dst + e);
        g_csr_src[atomicAdd(&g_cursor[d4.x], 1)] = s4.x;
        g_csr_src[atomicAdd(&g_cursor[d4.y], 1)] = s4.y;
        g_csr_src[atomicAdd(&g_cursor[d4.z], 1)] = s4.z;
        g_csr_src[atomicAdd(&g_cursor[d4.w], 1)] = s4.w;
    } else {
        for (; e < E; e++)
            g_csr_src[atomicAdd(&g_cursor[dst[e]], 1)] = src[e];
    }
}

// ============================================================================
// HMMA GEMM: g_A[r][c] = fp16( (X[r,:] @ W[:,c]) * rsqrt(max(deg_out[r],1)) )
// Block 128x64, 256 threads, K chunked by 32, padded smem stride 40 halfs.
// ============================================================================
#define XS 40

template<int K, bool HALF_IN>
__global__ void k_gemm_tc(const float* __restrict__ Xf, int n) {
    __shared__ __align__(16) __half sX[128 * XS];
    __shared__ __align__(16) __half sW[64 * XS];

    const __half* __restrict__ Wt = (K == 128) ? g_W1t : g_W2t;

    int tid = threadIdx.x;
    int lane = tid & 31;
    int warp = tid >> 5;
    int warp_m = warp & 3;
    int warp_n = warp >> 2;
    int g = lane >> 2;
    int tig = lane & 3;
    int row0 = blockIdx.x * 128;

    float acc[2][4][4];
#pragma unroll
    for (int mt = 0; mt < 2; mt++)
#pragma unroll
        for (int nt = 0; nt < 4; nt++)
#pragma unroll
            for (int c = 0; c < 4; c++) acc[mt][nt][c] = 0.f;

#pragma unroll
    for (int kc = 0; kc < K; kc += 32) {
        if (HALF_IN) {
#pragma unroll
            for (int p = 0; p < 2; p++) {
                int l = tid + p * 256;
                int r = l >> 2, q = l & 3;
                int gr = row0 + r;
                if (gr < n) {
                    *reinterpret_cast<uint4*>(&sX[r * XS + q * 8]) =
                        *reinterpret_cast<const uint4*>(g_B + (size_t)gr * 64 + kc + q * 8);
                }
            }
        } else {
#pragma unroll
            for (int p = 0; p < 4; p++) {
                int l = tid + p * 256;
                int r = l >> 3, c4 = l & 7;
                int gr = row0 + r;
                if (gr < n) {
                    float4 v = *reinterpret_cast<const float4*>(Xf + (size_t)gr * K + kc + c4 * 4);
                    *reinterpret_cast<__half2*>(&sX[r * XS + c4 * 4])     = __floats2half2_rn(v.x, v.y);
                    *reinterpret_cast<__half2*>(&sX[r * XS + c4 * 4 + 2]) = __floats2half2_rn(v.z, v.w);
                }
            }
        }
        {
            int r = tid >> 2, q = tid & 3;
            *reinterpret_cast<uint4*>(&sW[r * XS + q * 8]) =
                *reinterpret_cast<const uint4*>(Wt + (size_t)r * K + kc + q * 8);
        }
        __syncthreads();

#pragma unroll
        for (int k16 = 0; k16 < 32; k16 += 16) {
#pragma unroll
            for (int mt = 0; mt < 2; mt++) {
                int ar = warp_m * 32 + mt * 16;
                unsigned a0 = *reinterpret_cast<unsigned*>(&sX[(ar + g) * XS + k16 + tig * 2]);
                unsigned a1 = *reinterpret_cast<unsigned*>(&sX[(ar + g + 8) * XS + k16 + tig * 2]);
                unsigned a2 = *reinterpret_cast<unsigned*>(&sX[(ar + g) * XS + k16 + tig * 2 + 8]);
                unsigned a3 = *reinterpret_cast<unsigned*>(&sX[(ar + g + 8) * XS + k16 + tig * 2 + 8]);
#pragma unroll
                for (int nt = 0; nt < 4; nt++) {
                    int col = warp_n * 32 + nt * 8 + g;
                    unsigned b0 = *reinterpret_cast<unsigned*>(&sW[col * XS + k16 + tig * 2]);
                    unsigned b1 = *reinterpret_cast<unsigned*>(&sW[col * XS + k16 + tig * 2 + 8]);
                    float* c = acc[mt][nt];
                    asm volatile(
                        "mma.sync.aligned.m16n8k16.row.col.f32.f16.f16.f32 "
                        "{%0,%1,%2,%3},{%4,%5,%6,%7},{%8,%9},{%0,%1,%2,%3};"
                        : "+f"(c[0]), "+f"(c[1]), "+f"(c[2]), "+f"(c[3])
                        : "r"(a0), "r"(a1), "r"(a2), "r"(a3), "r"(b0), "r"(b1));
                }
            }
        }
        __syncthreads();
    }

#pragma unroll
    for (int mt = 0; mt < 2; mt++) {
        int row = row0 + warp_m * 32 + mt * 16 + g;
        float s0 = (row     < n) ? rsqrtf((float)max(g_deg_out[row], 1))     : 0.f;
        float s1 = (row + 8 < n) ? rsqrtf((float)max(g_deg_out[row + 8], 1)) : 0.f;
#pragma unroll
        for (int nt = 0; nt < 4; nt++) {
            int col = warp_n * 32 + nt * 8 + tig * 2;
            float* c = acc[mt][nt];
            if (row < n)
                *reinterpret_cast<__half2*>(g_A + (size_t)row * 64 + col) =
                    __floats2half2_rn(c[0] * s0, c[1] * s0);
            if (row + 8 < n)
                *reinterpret_cast<__half2*>(g_A + (size_t)(row + 8) * 64 + col) =
                    __floats2half2_rn(c[2] * s1, c[3] * s1);
        }
    }
}

// ============================================================================
// CSR aggregate, warp per node (100K warps). 8 lanes per edge; 16 edges in
// flight per iteration (4 independent uint4 chains). Segment = [ptr, ptr+deg).
// ============================================================================
template<int LAYER>
__global__ void k_agg(const float* __restrict__ bias, float* __restrict__ outp, int n) {
    int gw = (blockIdx.x * blockDim.x + threadIdx.x) >> 5;
    int lane = threadIdx.x & 31;
    if (gw >= n) return;

    int s0 = g_csr_ptr[gw];
    int deg = g_deg_in[gw];
    int s1 = s0 + deg;
    int sub = lane & 7;
    int grp = lane >> 3;

    float acc[8];
#pragma unroll
    for (int j = 0; j < 8; j++) acc[j] = 0.f;

    for (int base = s0; base < s1; base += 16) {
        uint4 h0 = make_uint4(0u, 0u, 0u, 0u);
        uint4 h1 = make_uint4(0u, 0u, 0u, 0u);
        uint4 h2 = make_uint4(0u, 0u, 0u, 0u);
        uint4 h3 = make_uint4(0u, 0u, 0u, 0u);
        int e0 = base + grp;
        int e1 = base + 4 + grp;
        int e2 = base + 8 + grp;
        int e3 = base + 12 + grp;
        if (e0 < s1) h0 = *reinterpret_cast<const uint4*>(g_A + (size_t)g_csr_src[e0] * 64 + sub * 8);
        if (e1 < s1) h1 = *reinterpret_cast<const uint4*>(g_A + (size_t)g_csr_src[e1] * 64 + sub * 8);
        if (e2 < s1) h2 = *reinterpret_cast<const uint4*>(g_A + (size_t)g_csr_src[e2] * 64 + sub * 8);
        if (e3 < s1) h3 = *reinterpret_cast<const uint4*>(g_A + (size_t)g_csr_src[e3] * 64 + sub * 8);
        const __half2* p0 = reinterpret_cast<const __half2*>(&h0);
        const __half2* p1 = reinterpret_cast<const __half2*>(&h1);
        const __half2* p2 = reinterpret_cast<const __half2*>(&h2);
        const __half2* p3 = reinterpret_cast<const __half2*>(&h3);
#pragma unroll
        for (int q = 0; q < 4; q++) {
            float2 f0 = __half22float2(p0[q]);
            float2 f1 = __half22float2(p1[q]);
            float2 f2 = __half22float2(p2[q]);
            float2 f3 = __half22float2(p3[q]);
            acc[q * 2]     += (f0.x + f1.x) + (f2.x + f3.x);
            acc[q * 2 + 1] += (f0.y + f1.y) + (f2.y + f3.y);
        }
    }

#pragma unroll
    for (int j = 0; j < 8; j++) {
        acc[j] += __shfl_xor_sync(0xffffffffu, acc[j], 8);
        acc[j] += __shfl_xor_sync(0xffffffffu, acc[j], 16);
    }

    if (grp == 0) {
        float sc = rsqrtf((float)max(deg, 1));
        const float* bp = bias + sub * 8;
        float o[8];
#pragma unroll
        for (int j = 0; j < 8; j++) {
            o[j] = fmaf(acc[j], sc, bp[j]);
            if (LAYER == 1) o[j] = fmaxf(o[j], 0.f);
        }
        if (LAYER == 1) {
            uint4 pack;
            __half2* hp = reinterpret_cast<__half2*>(&pack);
            hp[0] = __floats2half2_rn(o[0], o[1]);
            hp[1] = __floats2half2_rn(o[2], o[3]);
            hp[2] = __floats2half2_rn(o[4], o[5]);
            hp[3] = __floats2half2_rn(o[6], o[7]);
            *reinterpret_cast<uint4*>(g_B + (size_t)gw * 64 + sub * 8) = pack;
        } else {
            float* op = outp + (size_t)gw * 64 + sub * 8;
            *reinterpret_cast<float4*>(op)     = make_float4(o[0], o[1], o[2], o[3]);
            *reinterpret_cast<float4*>(op + 4) = make_float4(o[4], o[5], o[6], o[7]);
        }
    }
}

extern "C" void kernel_launch(void* const* d_in, const int* in_sizes, int n_in,
                              void* d_out, int out_size) {
    const float* x   = (const float*)d_in[0];
    const int*   src = (const int*)d_in[1];
    const int*   dst = (const int*)d_in[2];
    const float* W1  = (const float*)d_in[3];
    const float* b1  = (const float*)d_in[4];
    const float* W2  = (const float*)d_in[5];
    const float* b2  = (const float*)d_in[6];
    float* out = (float*)d_out;

    const int n = NN;
    const int E = in_sizes[1];

    const int T = 256;
    int grid_e4    = ((E + 3) / 4 + T - 1) / T;
    int grid_nodes = (n + T - 1) / T;
    int grid_gemm  = (n + 127) / 128;
    int grid_agg   = (n * 32 + T - 1) / T;

    cudaStream_t s1;
    cudaStreamCreateWithFlags(&s1, cudaStreamNonBlocking);
    cudaEvent_t evFork, evJoin;
    cudaEventCreateWithFlags(&evFork, cudaEventDisableTiming);
    cudaEventCreateWithFlags(&evJoin, cudaEventDisableTiming);

    // serial prefix: prep, fused degrees
    k_prep<<<grid_nodes, T>>>(W1, W2, n);
    k_deg<<<grid_e4, T>>>(src, dst, E);
    cudaEventRecord(evFork, 0);
    cudaStreamWaitEvent(s1, evFork, 0);

    // branch A (main): GEMM1
    k_gemm_tc<128, false><<<grid_gemm, T>>>(x, n);

    // branch B (s1): assign -> CSR fill
    k_assign<<<grid_nodes, T, 0, s1>>>(n);
    k_fill<<<grid_e4, T, 0, s1>>>(src, dst, E);
    cudaEventRecord(evJoin, s1);
    cudaStreamWaitEvent(0, evJoin, 0);

    // layer 1 aggregate, layer 2
    k_agg<1><<<grid_agg, T>>>(b1, nullptr, n);
    k_gemm_tc<64, true><<<grid_gemm, T>>>(nullptr, n);
    k_agg<2><<<grid_agg, T>>>(b2, out, n);

    cudaEventDestroy(evFork);
    cudaEventDestroy(evJoin);
    cudaStreamDestroy(s1);
}

// round 14
// speedup vs baseline: 1.2150x; 1.1317x over previous
#include <cuda_runtime.h>
#include <cuda_fp16.h>
#include <cuda_bf16.h>

// ============================================================================
// GCN 2-layer on GB300, round 13: ELL-style fixed-slot CSR.
//  - every node owns slots [64*i, 64*i+64); cursor init in prep (no histogram,
//    no assign kernel). deg_in recovered as cursor[i]-64*i after fill.
//  - agg reverted to R9's 8-edge inner loop (16-edge was -8us, R12).
//   prep -> fork{ deg_out -> gemm1  ||  fill } -> agg1 -> gemm2 -> agg2
// ============================================================================

#define NN   100000
#define SLOT 64
#define SLOT_SH 6

__device__ int   g_deg_out[NN];
__device__ int   g_cursor[NN];
__device__ int   g_csr_src[NN * SLOT];            // 25.6 MB, ELL buckets
__device__ __align__(16) __half g_A[NN * 64];     // gemm outputs (dout-scaled)
__device__ __align__(16) __half g_B[NN * 64];     // layer-1 hidden (relu out)
__device__ __align__(16) __half g_W1t[64 * 128];  // W1^T [n][k] half
__device__ __align__(16) __half g_W2t[64 * 64];   // W2^T [n][k] half

// ---- prep: zero deg_out, init ELL cursors, transpose/convert weights ----
__global__ void k_prep(const float* __restrict__ W1, const float* __restrict__ W2, int n) {
    int t = blockIdx.x * blockDim.x + threadIdx.x;
    if (t < n) {
        g_deg_out[t] = 0;
        g_cursor[t]  = t << SLOT_SH;
    }
    if (t < 64 * 128) {
        int nn_ = t >> 7, k = t & 127;
        g_W1t[t] = __float2half(W1[k * 64 + nn_]);
    } else if (t < 64 * 128 + 64 * 64) {
        int u = t - 64 * 128;
        int nn_ = u >> 6, k = u & 63;
        g_W2t[u] = __float2half(W2[k * 64 + nn_]);
    }
}

// ---- out-degree histogram: 4 edges/thread (gemm branch) ----
__global__ void k_deg_out(const int* __restrict__ src, int E) {
    int t = blockIdx.x * blockDim.x + threadIdx.x;
    int e = t * 4;
    if (e + 3 < E) {
        int4 s4 = *reinterpret_cast<const int4*>(src + e);
        atomicAdd(&g_deg_out[s4.x], 1);
        atomicAdd(&g_deg_out[s4.y], 1);
        atomicAdd(&g_deg_out[s4.z], 1);
        atomicAdd(&g_deg_out[s4.w], 1);
    } else {
        for (; e < E; e++) atomicAdd(&g_deg_out[src[e]], 1);
    }
}

// ---- ELL fill: 4 edges/thread; bucket src into dst's fixed 64-slot segment ----
__global__ void k_fill(const int* __restrict__ src, const int* __restrict__ dst, int E) {
    int t = blockIdx.x * blockDim.x + threadIdx.x;
    int e = t * 4;
    if (e + 3 < E) {
        int4 s4 = *reinterpret_cast<const int4*>(src + e);
        int4 d4 = *reinterpret_cast<const int4*>(dst + e);
        int p0 = atomicAdd(&g_cursor[d4.x], 1);
        int p1 = atomicAdd(&g_cursor[d4.y], 1);
        int p2 = atomicAdd(&g_cursor[d4.z], 1);
        int p3 = atomicAdd(&g_cursor[d4.w], 1);
        if (p0 < (d4.x << SLOT_SH) + SLOT) g_csr_src[p0] = s4.x;
        if (p1 < (d4.y << SLOT_SH) + SLOT) g_csr_src[p1] = s4.y;
        if (p2 < (d4.z << SLOT_SH) + SLOT) g_csr_src[p2] = s4.z;
        if (p3 < (d4.w << SLOT_SH) + SLOT) g_csr_src[p3] = s4.w;
    } else {
        for (; e < E; e++) {
            int d = dst[e];
            int p = atomicAdd(&g_cursor[d], 1);
            if (p < (d << SLOT_SH) + SLOT) g_csr_src[p] = src[e];
        }
    }
}

// ============================================================================
// HMMA GEMM: g_A[r][c] = fp16( (X[r,:] @ W[:,c]) * rsqrt(max(deg_out[r],1)) )
// Block 128x64, 256 threads, K chunked by 32, padded smem stride 40 halfs.
// ============================================================================
#define XS 40

template<int K, bool HALF_IN>
__global__ void k_gemm_tc(const float* __restrict__ Xf, int n) {
    __shared__ __align__(16) __half sX[128 * XS];
    __shared__ __align__(16) __half sW[64 * XS];

    const __half* __restrict__ Wt = (K == 128) ? g_W1t : g_W2t;

    int tid = threadIdx.x;
    int lane = tid & 31;
    int warp = tid >> 5;
    int warp_m = warp & 3;
    int warp_n = warp >> 2;
    int g = lane >> 2;
    int tig = lane & 3;
    int row0 = blockIdx.x * 128;

    float acc[2][4][4];
#pragma unroll
    for (int mt = 0; mt < 2; mt++)
#pragma unroll
        for (int nt = 0; nt < 4; nt++)
#pragma unroll
            for (int c = 0; c < 4; c++) acc[mt][nt][c] = 0.f;

#pragma unroll
    for (int kc = 0; kc < K; kc += 32) {
        if (HALF_IN) {
#pragma unroll
            for (int p = 0; p < 2; p++) {
                int l = tid + p * 256;
                int r = l >> 2, q = l & 3;
                int gr = row0 + r;
                if (gr < n) {
                    *reinterpret_cast<uint4*>(&sX[r * XS + q * 8]) =
                        *reinterpret_cast<const uint4*>(g_B + (size_t)gr * 64 + kc + q * 8);
                }
            }
        } else {
#pragma unroll
            for (int p = 0; p < 4; p++) {
                int l = tid + p * 256;
                int r = l >> 3, c4 = l & 7;
                int gr = row0 + r;
                if (gr < n) {
                    float4 v = *reinterpret_cast<const float4*>(Xf + (size_t)gr * K + kc + c4 * 4);
                    *reinterpret_cast<__half2*>(&sX[r * XS + c4 * 4])     = __floats2half2_rn(v.x, v.y);
                    *reinterpret_cast<__half2*>(&sX[r * XS + c4 * 4 + 2]) = __floats2half2_rn(v.z, v.w);
                }
            }
        }
        {
            int r = tid >> 2, q = tid & 3;
            *reinterpret_cast<uint4*>(&sW[r * XS + q * 8]) =
                *reinterpret_cast<const uint4*>(Wt + (size_t)r * K + kc + q * 8);
        }
        __syncthreads();

#pragma unroll
        for (int k16 = 0; k16 < 32; k16 += 16) {
#pragma unroll
            for (int mt = 0; mt < 2; mt++) {
                int ar = warp_m * 32 + mt * 16;
                unsigned a0 = *reinterpret_cast<unsigned*>(&sX[(ar + g) * XS + k16 + tig * 2]);
                unsigned a1 = *reinterpret_cast<unsigned*>(&sX[(ar + g + 8) * XS + k16 + tig * 2]);
                unsigned a2 = *reinterpret_cast<unsigned*>(&sX[(ar + g) * XS + k16 + tig * 2 + 8]);
                unsigned a3 = *reinterpret_cast<unsigned*>(&sX[(ar + g + 8) * XS + k16 + tig * 2 + 8]);
#pragma unroll
                for (int nt = 0; nt < 4; nt++) {
                    int col = warp_n * 32 + nt * 8 + g;
                    unsigned b0 = *reinterpret_cast<unsigned*>(&sW[col * XS + k16 + tig * 2]);
                    unsigned b1 = *reinterpret_cast<unsigned*>(&sW[col * XS + k16 + tig * 2 + 8]);
                    float* c = acc[mt][nt];
                    asm volatile(
                        "mma.sync.aligned.m16n8k16.row.col.f32.f16.f16.f32 "
                        "{%0,%1,%2,%3},{%4,%5,%6,%7},{%8,%9},{%0,%1,%2,%3};"
                        : "+f"(c[0]), "+f"(c[1]), "+f"(c[2]), "+f"(c[3])
                        : "r"(a0), "r"(a1), "r"(a2), "r"(a3), "r"(b0), "r"(b1));
                }
            }
        }
        __syncthreads();
    }

#pragma unroll
    for (int mt = 0; mt < 2; mt++) {
        int row = row0 + warp_m * 32 + mt * 16 + g;
        float s0 = (row     < n) ? rsqrtf((float)max(g_deg_out[row], 1))     : 0.f;
        float s1 = (row + 8 < n) ? rsqrtf((float)max(g_deg_out[row + 8], 1)) : 0.f;
#pragma unroll
        for (int nt = 0; nt < 4; nt++) {
            int col = warp_n * 32 + nt * 8 + tig * 2;
            float* c = acc[mt][nt];
            if (row < n)
                *reinterpret_cast<__half2*>(g_A + (size_t)row * 64 + col) =
                    __floats2half2_rn(c[0] * s0, c[1] * s0);
            if (row + 8 < n)
                *reinterpret_cast<__half2*>(g_A + (size_t)(row + 8) * 64 + col) =
                    __floats2half2_rn(c[2] * s1, c[3] * s1);
        }
    }
}

// ============================================================================
// ELL aggregate, warp per node (100K warps). 8 lanes per edge (lane loads
// uint4 = 8 halfs), 8 edges in flight (R9 loop). Segment = [64*gw, cursor[gw]).
// ============================================================================
template<int LAYER>
__global__ void k_agg(const float* __restrict__ bias, float* __restrict__ outp, int n) {
    int gw = (blockIdx.x * blockDim.x + threadIdx.x) >> 5;
    int lane = threadIdx.x & 31;
    if (gw >= n) return;

    int s0 = gw << SLOT_SH;
    int s1 = min(g_cursor[gw], s0 + SLOT);
    int deg = s1 - s0;
    int sub = lane & 7;
    int grp = lane >> 3;

    float acc[8];
#pragma unroll
    for (int j = 0; j < 8; j++) acc[j] = 0.f;

    for (int base = s0; base < s1; base += 8) {
        int e0 = base + grp;
        int e1 = base + 4 + grp;
        uint4 h0 = make_uint4(0u, 0u, 0u, 0u);
        uint4 h1 = make_uint4(0u, 0u, 0u, 0u);
        if (e0 < s1)
            h0 = *reinterpret_cast<const uint4*>(g_A + (size_t)g_csr_src[e0] * 64 + sub * 8);
        if (e1 < s1)
            h1 = *reinterpret_cast<const uint4*>(g_A + (size_t)g_csr_src[e1] * 64 + sub * 8);
        const __half2* p0 = reinterpret_cast<const __half2*>(&h0);
        const __half2* p1 = reinterpret_cast<const __half2*>(&h1);
#pragma unroll
        for (int q = 0; q < 4; q++) {
            float2 f0 = __half22float2(p0[q]);
            float2 f1 = __half22float2(p1[q]);
            acc[q * 2]     += f0.x + f1.x;
            acc[q * 2 + 1] += f0.y + f1.y;
        }
    }

#pragma unroll
    for (int j = 0; j < 8; j++) {
        acc[j] += __shfl_xor_sync(0xffffffffu, acc[j], 8);
        acc[j] += __shfl_xor_sync(0xffffffffu, acc[j], 16);
    }

    if (grp == 0) {
        float sc = rsqrtf((float)max(deg, 1));
        const float* bp = bias + sub * 8;
        float o[8];
#pragma unroll
        for (int j = 0; j < 8; j++) {
            o[j] = fmaf(acc[j], sc, bp[j]);
            if (LAYER == 1) o[j] = fmaxf(o[j], 0.f);
        }
        if (LAYER == 1) {
            uint4 pack;
            __half2* hp = reinterpret_cast<__half2*>(&pack);
            hp[0] = __floats2half2_rn(o[0], o[1]);
            hp[1] = __floats2half2_rn(o[2], o[3]);
            hp[2] = __floats2half2_rn(o[4], o[5]);
            hp[3] = __floats2half2_rn(o[6], o[7]);
            *reinterpret_cast<uint4*>(g_B + (size_t)gw * 64 + sub * 8) = pack;
        } else {
            float* op = outp + (size_t)gw * 64 + sub * 8;
            *reinterpret_cast<float4*>(op)     = make_float4(o[0], o[1], o[2], o[3]);
            *reinterpret_cast<float4*>(op + 4) = make_float4(o[4], o[5], o[6], o[7]);
        }
    }
}

extern "C" void kernel_launch(void* const* d_in, const int* in_sizes, int n_in,
                              void* d_out, int out_size) {
    const float* x   = (const float*)d_in[0];
    const int*   src = (const int*)d_in[1];
    const int*   dst = (const int*)d_in[2];
    const float* W1  = (const float*)d_in[3];
    const float* b1  = (const float*)d_in[4];
    const float* W2  = (const float*)d_in[5];
    const float* b2  = (const float*)d_in[6];
    float* out = (float*)d_out;

    const int n = NN;
    const int E = in_sizes[1];

    const int T = 256;
    int grid_e4    = ((E + 3) / 4 + T - 1) / T;
    int grid_nodes = (n + T - 1) / T;
    int grid_gemm  = (n + 127) / 128;
    int grid_agg   = (n * 32 + T - 1) / T;

    cudaStream_t s1;
    cudaStreamCreateWithFlags(&s1, cudaStreamNonBlocking);
    cudaEvent_t evFork, evJoin;
    cudaEventCreateWithFlags(&evFork, cudaEventDisableTiming);
    cudaEventCreateWithFlags(&evJoin, cudaEventDisableTiming);

    // prep (zero deg_out, init ELL cursors, weights), then fork
    k_prep<<<grid_nodes, T>>>(W1, W2, n);
    cudaEventRecord(evFork, 0);
    cudaStreamWaitEvent(s1, evFork, 0);

    // branch A (main): out-degree histogram -> GEMM1
    k_deg_out<<<grid_e4, T>>>(src, E);
    k_gemm_tc<128, false><<<grid_gemm, T>>>(x, n);

    // branch B (s1): ELL fill (needs only cursors from prep)
    k_fill<<<grid_e4, T, 0, s1>>>(src, dst, E);
    cudaEventRecord(evJoin, s1);
    cudaStreamWaitEvent(0, evJoin, 0);

    // layer 1 aggregate, layer 2
    k_agg<1><<<grid_agg, T>>>(b1, nullptr, n);
    k_gemm_tc<64, true><<<grid_gemm, T>>>(nullptr, n);
    k_agg<2><<<grid_agg, T>>>(b2, out, n);

    cudaEventDestroy(evFork);
    cudaEventDestroy(evJoin);
    cudaStreamDestroy(s1);
}

// round 15
// speedup vs baseline: 1.2153x; 1.0003x over previous
#include <cuda_runtime.h>
#include <cuda_fp16.h>
#include <cuda_bf16.h>

// ============================================================================
// GCN 2-layer on GB300, round 14:
//  - gemm1 unscaled, launches right after prep (no deg_out dependency)
//  - k_fill fuses the out-degree histogram (one edge-list pass deleted)
//  - k_scaleA applies dout^-1/2 to A after the join (L2-resident, ~3us)
//  - agg: unguarded fast path for full 8-edge batches
//   prep -> fork{ gemm1 || fill+degout } -> scaleA -> agg1 -> gemm2 -> agg2
// ============================================================================

#define NN   100000
#define SLOT 64
#define SLOT_SH 6

__device__ int   g_deg_out[NN];
__device__ int   g_cursor[NN];
__device__ int   g_csr_src[NN * SLOT];            // 25.6 MB, ELL buckets
__device__ __align__(16) __half g_A[NN * 64];     // gemm outputs
__device__ __align__(16) __half g_B[NN * 64];     // layer-1 hidden (relu out)
__device__ __align__(16) __half g_W1t[64 * 128];  // W1^T [n][k] half
__device__ __align__(16) __half g_W2t[64 * 64];   // W2^T [n][k] half

// ---- prep: zero deg_out, init ELL cursors, transpose/convert weights ----
__global__ void k_prep(const float* __restrict__ W1, const float* __restrict__ W2, int n) {
    int t = blockIdx.x * blockDim.x + threadIdx.x;
    if (t < n) {
        g_deg_out[t] = 0;
        g_cursor[t]  = t << SLOT_SH;
    }
    if (t < 64 * 128) {
        int nn_ = t >> 7, k = t & 127;
        g_W1t[t] = __float2half(W1[k * 64 + nn_]);
    } else if (t < 64 * 128 + 64 * 64) {
        int u = t - 64 * 128;
        int nn_ = u >> 6, k = u & 63;
        g_W2t[u] = __float2half(W2[k * 64 + nn_]);
    }
}

// ---- fused ELL fill + out-degree histogram: 4 edges/thread ----
__global__ void k_fill(const int* __restrict__ src, const int* __restrict__ dst, int E) {
    int t = blockIdx.x * blockDim.x + threadIdx.x;
    int e = t * 4;
    if (e + 3 < E) {
        int4 s4 = *reinterpret_cast<const int4*>(src + e);
        int4 d4 = *reinterpret_cast<const int4*>(dst + e);
        atomicAdd(&g_deg_out[s4.x], 1);
        atomicAdd(&g_deg_out[s4.y], 1);
        atomicAdd(&g_deg_out[s4.z], 1);
        atomicAdd(&g_deg_out[s4.w], 1);
        int p0 = atomicAdd(&g_cursor[d4.x], 1);
        int p1 = atomicAdd(&g_cursor[d4.y], 1);
        int p2 = atomicAdd(&g_cursor[d4.z], 1);
        int p3 = atomicAdd(&g_cursor[d4.w], 1);
        if (p0 < (d4.x << SLOT_SH) + SLOT) g_csr_src[p0] = s4.x;
        if (p1 < (d4.y << SLOT_SH) + SLOT) g_csr_src[p1] = s4.y;
        if (p2 < (d4.z << SLOT_SH) + SLOT) g_csr_src[p2] = s4.z;
        if (p3 < (d4.w << SLOT_SH) + SLOT) g_csr_src[p3] = s4.w;
    } else {
        for (; e < E; e++) {
            int s = src[e];
            int d = dst[e];
            atomicAdd(&g_deg_out[s], 1);
            int p = atomicAdd(&g_cursor[d], 1);
            if (p < (d << SLOT_SH) + SLOT) g_csr_src[p] = s;
        }
    }
}

// ---- scale A rows by rsqrt(max(deg_out,1)): 8 halfs per thread ----
__global__ void k_scaleA(int n) {
    int t = blockIdx.x * blockDim.x + threadIdx.x;
    if (t >= n * 8) return;
    int row = t >> 3;
    float sc = rsqrtf((float)max(g_deg_out[row], 1));
    uint4 v = *reinterpret_cast<uint4*>(g_A + (size_t)t * 8);
    __half2* hp = reinterpret_cast<__half2*>(&v);
#pragma unroll
    for (int q = 0; q < 4; q++) {
        float2 f = __half22float2(hp[q]);
        hp[q] = __floats2half2_rn(f.x * sc, f.y * sc);
    }
    *reinterpret_cast<uint4*>(g_A + (size_t)t * 8) = v;
}

// ============================================================================
// HMMA GEMM. SCALE: multiply rows by rsqrt(max(deg_out,1)) in epilogue.
// Block 128x64, 256 threads, K chunked by 32, padded smem stride 40 halfs.
// ============================================================================
#define XS 40

template<int K, bool HALF_IN, bool SCALE>
__global__ void k_gemm_tc(const float* __restrict__ Xf, int n) {
    __shared__ __align__(16) __half sX[128 * XS];
    __shared__ __align__(16) __half sW[64 * XS];

    const __half* __restrict__ Wt = (K == 128) ? g_W1t : g_W2t;

    int tid = threadIdx.x;
    int lane = tid & 31;
    int warp = tid >> 5;
    int warp_m = warp & 3;
    int warp_n = warp >> 2;
    int g = lane >> 2;
    int tig = lane & 3;
    int row0 = blockIdx.x * 128;

    float acc[2][4][4];
#pragma unroll
    for (int mt = 0; mt < 2; mt++)
#pragma unroll
        for (int nt = 0; nt < 4; nt++)
#pragma unroll
            for (int c = 0; c < 4; c++) acc[mt][nt][c] = 0.f;

#pragma unroll
    for (int kc = 0; kc < K; kc += 32) {
        if (HALF_IN) {
#pragma unroll
            for (int p = 0; p < 2; p++) {
                int l = tid + p * 256;
                int r = l >> 2, q = l & 3;
                int gr = row0 + r;
                if (gr < n) {
                    *reinterpret_cast<uint4*>(&sX[r * XS + q * 8]) =
                        *reinterpret_cast<const uint4*>(g_B + (size_t)gr * 64 + kc + q * 8);
                }
            }
        } else {
#pragma unroll
            for (int p = 0; p < 4; p++) {
                int l = tid + p * 256;
                int r = l >> 3, c4 = l & 7;
                int gr = row0 + r;
                if (gr < n) {
                    float4 v = *reinterpret_cast<const float4*>(Xf + (size_t)gr * K + kc + c4 * 4);
                    *reinterpret_cast<__half2*>(&sX[r * XS + c4 * 4])     = __floats2half2_rn(v.x, v.y);
                    *reinterpret_cast<__half2*>(&sX[r * XS + c4 * 4 + 2]) = __floats2half2_rn(v.z, v.w);
                }
            }
        }
        {
            int r = tid >> 2, q = tid & 3;
            *reinterpret_cast<uint4*>(&sW[r * XS + q * 8]) =
                *reinterpret_cast<const uint4*>(Wt + (size_t)r * K + kc + q * 8);
        }
        __syncthreads();

#pragma unroll
        for (int k16 = 0; k16 < 32; k16 += 16) {
#pragma unroll
            for (int mt = 0; mt < 2; mt++) {
                int ar = warp_m * 32 + mt * 16;
                unsigned a0 = *reinterpret_cast<unsigned*>(&sX[(ar + g) * XS + k16 + tig * 2]);
                unsigned a1 = *reinterpret_cast<unsigned*>(&sX[(ar + g + 8) * XS + k16 + tig * 2]);
                unsigned a2 = *reinterpret_cast<unsigned*>(&sX[(ar + g) * XS + k16 + tig * 2 + 8]);
                unsigned a3 = *reinterpret_cast<unsigned*>(&sX[(ar + g + 8) * XS + k16 + tig * 2 + 8]);
#pragma unroll
                for (int nt = 0; nt < 4; nt++) {
                    int col = warp_n * 32 + nt * 8 + g;
                    unsigned b0 = *reinterpret_cast<unsigned*>(&sW[col * XS + k16 + tig * 2]);
                    unsigned b1 = *reinterpret_cast<unsigned*>(&sW[col * XS + k16 + tig * 2 + 8]);
                    float* c = acc[mt][nt];
                    asm volatile(
                        "mma.sync.aligned.m16n8k16.row.col.f32.f16.f16.f32 "
                        "{%0,%1,%2,%3},{%4,%5,%6,%7},{%8,%9},{%0,%1,%2,%3};"
                        : "+f"(c[0]), "+f"(c[1]), "+f"(c[2]), "+f"(c[3])
                        : "r"(a0), "r"(a1), "r"(a2), "r"(a3), "r"(b0), "r"(b1));
                }
            }
        }
        __syncthreads();
    }

#pragma unroll
    for (int mt = 0; mt < 2; mt++) {
        int row = row0 + warp_m * 32 + mt * 16 + g;
        float s0 = 1.f, s1 = 1.f;
        if (SCALE) {
            s0 = (row     < n) ? rsqrtf((float)max(g_deg_out[row], 1))     : 0.f;
            s1 = (row + 8 < n) ? rsqrtf((float)max(g_deg_out[row + 8], 1)) : 0.f;
        }
#pragma unroll
        for (int nt = 0; nt < 4; nt++) {
            int col = warp_n * 32 + nt * 8 + tig * 2;
            float* c = acc[mt][nt];
            if (row < n)
                *reinterpret_cast<__half2*>(g_A + (size_t)row * 64 + col) =
                    __floats2half2_rn(c[0] * s0, c[1] * s0);
            if (row + 8 < n)
                *reinterpret_cast<__half2*>(g_A + (size_t)(row + 8) * 64 + col) =
                    __floats2half2_rn(c[2] * s1, c[3] * s1);
        }
    }
}

// ============================================================================
// ELL aggregate, warp per node. 8 lanes/edge, 8 edges in flight; unguarded
// fast path for full batches. Segment = [64*gw, cursor[gw]).
// ============================================================================
template<int LAYER>
__global__ void k_agg(const float* __restrict__ bias, float* __restrict__ outp, int n) {
    int gw = (blockIdx.x * blockDim.x + threadIdx.x) >> 5;
    int lane = threadIdx.x & 31;
    if (gw >= n) return;

    int s0 = gw << SLOT_SH;
    int s1 = min(g_cursor[gw], s0 + SLOT);
    int deg = s1 - s0;
    int sub = lane & 7;
    int grp = lane >> 3;

    float acc[8];
#pragma unroll
    for (int j = 0; j < 8; j++) acc[j] = 0.f;

    int base = s0;
    // fast path: full 8-edge batches, no bounds checks
    for (; base + 8 <= s1; base += 8) {
        uint4 h0 = *reinterpret_cast<const uint4*>(g_A + (size_t)g_csr_src[base + grp] * 64 + sub * 8);
        uint4 h1 = *reinterpret_cast<const uint4*>(g_A + (size_t)g_csr_src[base + 4 + grp] * 64 + sub * 8);
        const __half2* p0 = reinterpret_cast<const __half2*>(&h0);
        const __half2* p1 = reinterpret_cast<const __half2*>(&h1);
#pragma unroll
        for (int q = 0; q < 4; q++) {
            float2 f0 = __half22float2(p0[q]);
            float2 f1 = __half22float2(p1[q]);
            acc[q * 2]     += f0.x + f1.x;
            acc[q * 2 + 1] += f0.y + f1.y;
        }
    }
    // tail
    if (base < s1) {
        int e0 = base + grp;
        int e1 = base + 4 + grp;
        uint4 h0 = make_uint4(0u, 0u, 0u, 0u);
        uint4 h1 = make_uint4(0u, 0u, 0u, 0u);
        if (e0 < s1)
            h0 = *reinterpret_cast<const uint4*>(g_A + (size_t)g_csr_src[e0] * 64 + sub * 8);
        if (e1 < s1)
            h1 = *reinterpret_cast<const uint4*>(g_A + (size_t)g_csr_src[e1] * 64 + sub * 8);
        const __half2* p0 = reinterpret_cast<const __half2*>(&h0);
        const __half2* p1 = reinterpret_cast<const __half2*>(&h1);
#pragma unroll
        for (int q = 0; q < 4; q++) {
            float2 f0 = __half22float2(p0[q]);
            float2 f1 = __half22float2(p1[q]);
            acc[q * 2]     += f0.x + f1.x;
            acc[q * 2 + 1] += f0.y + f1.y;
        }
    }

#pragma unroll
    for (int j = 0; j < 8; j++) {
        acc[j] += __shfl_xor_sync(0xffffffffu, acc[j], 8);
        acc[j] += __shfl_xor_sync(0xffffffffu, acc[j], 16);
    }

    if (grp == 0) {
        float sc = rsqrtf((float)max(deg, 1));
        const float* bp = bias + sub * 8;
        float o[8];
#pragma unroll
        for (int j = 0; j < 8; j++) {
            o[j] = fmaf(acc[j], sc, bp[j]);
            if (LAYER == 1) o[j] = fmaxf(o[j], 0.f);
        }
        if (LAYER == 1) {
            uint4 pack;
            __half2* hp = reinterpret_cast<__half2*>(&pack);
            hp[0] = __floats2half2_rn(o[0], o[1]);
            hp[1] = __floats2half2_rn(o[2], o[3]);
            hp[2] = __floats2half2_rn(o[4], o[5]);
            hp[3] = __floats2half2_rn(o[6], o[7]);
            *reinterpret_cast<uint4*>(g_B + (size_t)gw * 64 + sub * 8) = pack;
        } else {
            float* op = outp + (size_t)gw * 64 + sub * 8;
            *reinterpret_cast<float4*>(op)     = make_float4(o[0], o[1], o[2], o[3]);
            *reinterpret_cast<float4*>(op + 4) = make_float4(o[4], o[5], o[6], o[7]);
        }
    }
}

extern "C" void kernel_launch(void* const* d_in, const int* in_sizes, int n_in,
                              void* d_out, int out_size) {
    const float* x   = (const float*)d_in[0];
    const int*   src = (const int*)d_in[1];
    const int*   dst = (const int*)d_in[2];
    const float* W1  = (const float*)d_in[3];
    const float* b1  = (const float*)d_in[4];
    const float* W2  = (const float*)d_in[5];
    const float* b2  = (const float*)d_in[6];
    float* out = (float*)d_out;

    const int n = NN;
    const int E = in_sizes[1];

    const int T = 256;
    int grid_e4    = ((E + 3) / 4 + T - 1) / T;
    int grid_nodes = (n + T - 1) / T;
    int grid_gemm  = (n + 127) / 128;
    int grid_agg   = (n * 32 + T - 1) / T;
    int grid_scale = (n * 8 + T - 1) / T;

    cudaStream_t s1;
    cudaStreamCreateWithFlags(&s1, cudaStreamNonBlocking);
    cudaEvent_t evFork, evJoin;
    cudaEventCreateWithFlags(&evFork, cudaEventDisableTiming);
    cudaEventCreateWithFlags(&evJoin, cudaEventDisableTiming);

    // prep, then fork
    k_prep<<<grid_nodes, T>>>(W1, W2, n);
    cudaEventRecord(evFork, 0);
    cudaStreamWaitEvent(s1, evFork, 0);

    // branch A (main): GEMM1 unscaled (no deg dependency)
    k_gemm_tc<128, false, false><<<grid_gemm, T>>>(x, n);

    // branch B (s1): fused ELL fill + out-degree histogram
    k_fill<<<grid_e4, T, 0, s1>>>(src, dst, E);
    cudaEventRecord(evJoin, s1);
    cudaStreamWaitEvent(0, evJoin, 0);

    // scale A by dout^-1/2, then layer 1 aggregate, layer 2
    k_scaleA<<<grid_scale, T>>>(n);
    k_agg<1><<<grid_agg, T>>>(b1, nullptr, n);
    k_gemm_tc<64, true, true><<<grid_gemm, T>>>(nullptr, n);
    k_agg<2><<<grid_agg, T>>>(b2, out, n);

    cudaEventDestroy(evFork);
    cudaEventDestroy(evJoin);
    cudaStreamDestroy(s1);
}